// round 3
// baseline (speedup 1.0000x reference)
#include <cuda_runtime.h>
#include <math.h>

// ---------------------------------------------------------------------------
// Problem constants
//   T=32, N=16, TN=512, C=4, HW=124, A=6, H=512
//   conv1: 4->32, 8x8 s4 : 124 -> 30
//   conv2: 32->64, 4x4 s2: 30 -> 14
//   conv3: 64->32, 3x3 s1: 14 -> 12
//   fc: 4608 -> 512 ; GRU H=512 ; heads A=6 + value
// Output (9728 f32): value[512] | action_log_probs[512] | entropy[512] | states_out[16*512]
// ---------------------------------------------------------------------------

// -------------------- device scratch (no allocations allowed) --------------
__device__ float g_act1[32 * 512 * 900];    // conv1 out, layout [oc][img][oy*30+ox]
__device__ float g_act2[64 * 512 * 196];    // conv2 out, layout [oc][img][s]
__device__ float g_act3[32 * 512 * 144];    // conv3 out, layout [oc][img][s]
__device__ float g_xfc[512 * 4608];         // fc input  [n][4608]
__device__ float g_part[12 * 512 * 512];    // split-K partials (shared fc/gi)
__device__ float g_x[512 * 512];            // fc output (relu)
__device__ float g_gi[512 * 1536];          // input gates [t*16+n][1536]
__device__ float g_h[2][16 * 512];          // GRU hidden ping-pong
__device__ float g_outs[512 * 512];         // GRU outputs [t*16+n][512]

// ---------------------------------------------------------------------------
// Implicit-im2col conv GEMM:  out[m][p] = relu( sum_k W[m][k] * col[k][p] + b[m] )
//   k = (c, ky, kx), p = (img, oy, ox); all geometry compile-time.
//   BM == OC (single block row). Register tile TM x TN.
// ---------------------------------------------------------------------------
template<int C, int KK, int IH, int IW, int OH, int OW, int STRIDE,
         int CH_STRIDE, int IMG_STRIDE,
         int BM, int BN, int BK, int TM, int TN, int NTHREADS, bool SCALE>
__launch_bounds__(NTHREADS)
__global__ void conv_gemm_kernel(const float* __restrict__ W,
                                 const float* __restrict__ bias,
                                 const float* __restrict__ in,
                                 float* __restrict__ out)
{
    constexpr int K    = C * KK * KK;
    constexpr int SPER = OH * OW;          // spatial per image
    constexpr int NTOT = 512 * SPER;

    __shared__ float As[BK][BM];
    __shared__ float Bs[BK][BN];
    __shared__ int   nb[BN];

    const int tid = threadIdx.x;
    const int bn0 = blockIdx.x * BN;

    // per-column base offsets (image + spatial origin), constant over k tiles
    for (int i = tid; i < BN; i += NTHREADS) {
        int ng  = bn0 + i;
        int img = ng / SPER;
        int r   = ng - img * SPER;
        int oy  = r / OW;
        int ox  = r - oy * OW;
        nb[i] = img * IMG_STRIDE + oy * STRIDE * IW + ox * STRIDE;
    }
    __syncthreads();

    constexpr int TCOLS = BN / TN;
    const int tidn = tid % TCOLS;
    const int tidm = tid / TCOLS;
    const int tm0  = tidm * TM, tn0 = tidn * TN;

    float acc[TM][TN];
#pragma unroll
    for (int i = 0; i < TM; i++)
#pragma unroll
        for (int j = 0; j < TN; j++) acc[i][j] = 0.f;

    for (int k0 = 0; k0 < K; k0 += BK) {
        // A tile (weights)
        for (int i = tid; i < BM * BK; i += NTHREADS) {
            int m = i / BK, kk = i - m * BK;
            As[kk][m] = W[m * K + k0 + kk];
        }
        // B tile: implicit im2col gather
        for (int i = tid; i < BK * BN; i += NTHREADS) {
            int kk = i / BN, nn = i - kk * BN;
            int kg = k0 + kk;
            int c  = kg / (KK * KK);
            int r  = kg - c * (KK * KK);
            int ky = r / KK, kx = r - ky * KK;
            float v = __ldg(&in[nb[nn] + c * CH_STRIDE + ky * IW + kx]);
            Bs[kk][nn] = SCALE ? v * (1.0f / 255.0f) : v;
        }
        __syncthreads();
#pragma unroll
        for (int kk = 0; kk < BK; kk++) {
            float ra[TM], rb[TN];
#pragma unroll
            for (int i = 0; i < TM; i++) ra[i] = As[kk][tm0 + i];
#pragma unroll
            for (int j = 0; j < TN; j++) rb[j] = Bs[kk][tn0 + j];
#pragma unroll
            for (int i = 0; i < TM; i++)
#pragma unroll
                for (int j = 0; j < TN; j++)
                    acc[i][j] = fmaf(ra[i], rb[j], acc[i][j]);
        }
        __syncthreads();
    }

#pragma unroll
    for (int i = 0; i < TM; i++) {
        int m = tm0 + i;
        float b = bias[m];
#pragma unroll
        for (int j = 0; j < TN; j++) {
            int n = bn0 + tn0 + j;
            out[(size_t)m * NTOT + n] = fmaxf(acc[i][j] + b, 0.f);
        }
    }
}

// ---------------------------------------------------------------------------
// Split-K NT GEMM: partial[s] = A[M][K] * B[N][K]^T over k slice s.
// ---------------------------------------------------------------------------
template<int BM, int BN, int BK, int TM, int TN, int NTHREADS>
__launch_bounds__(NTHREADS)
__global__ void gemm_nt_splitk(const float* __restrict__ A, const float* __restrict__ B,
                               float* __restrict__ partial, int M, int N, int K, int kps)
{
    __shared__ float As[BK][BM];
    __shared__ float Bs[BK][BN];
    const int tid = threadIdx.x;
    const int m0 = blockIdx.y * BM, n0 = blockIdx.x * BN;
    const int kbeg = blockIdx.z * kps;

    constexpr int TCOLS = BN / TN;
    const int tidn = tid % TCOLS, tidm = tid / TCOLS;
    const int tm0 = tidm * TM, tn0 = tidn * TN;

    float acc[TM][TN];
#pragma unroll
    for (int i = 0; i < TM; i++)
#pragma unroll
        for (int j = 0; j < TN; j++) acc[i][j] = 0.f;

    for (int k0 = kbeg; k0 < kbeg + kps; k0 += BK) {
        for (int i = tid; i < BM * BK; i += NTHREADS) {
            int m = i / BK, kk = i - m * BK;
            As[kk][m] = A[(size_t)(m0 + m) * K + k0 + kk];
        }
        for (int i = tid; i < BN * BK; i += NTHREADS) {
            int n = i / BK, kk = i - n * BK;
            Bs[kk][n] = B[(size_t)(n0 + n) * K + k0 + kk];
        }
        __syncthreads();
#pragma unroll
        for (int kk = 0; kk < BK; kk++) {
            float ra[TM], rb[TN];
#pragma unroll
            for (int i = 0; i < TM; i++) ra[i] = As[kk][tm0 + i];
#pragma unroll
            for (int j = 0; j < TN; j++) rb[j] = Bs[kk][tn0 + j];
#pragma unroll
            for (int i = 0; i < TM; i++)
#pragma unroll
                for (int j = 0; j < TN; j++)
                    acc[i][j] = fmaf(ra[i], rb[j], acc[i][j]);
        }
        __syncthreads();
    }

    float* p = partial + (size_t)blockIdx.z * M * N;
#pragma unroll
    for (int i = 0; i < TM; i++)
#pragma unroll
        for (int j = 0; j < TN; j++)
            p[(size_t)(m0 + tm0 + i) * N + (n0 + tn0 + j)] = acc[i][j];
}

__global__ void finalize_kernel(const float* __restrict__ partial, int S,
                                const float* __restrict__ bias,
                                float* __restrict__ out, int MN, int N, int relu)
{
    for (int i = blockIdx.x * blockDim.x + threadIdx.x; i < MN;
         i += gridDim.x * blockDim.x) {
        float v = 0.f;
        for (int s = 0; s < S; s++) v += partial[(size_t)s * MN + i];
        v += bias[i % N];
        out[i] = relu ? fmaxf(v, 0.f) : v;
    }
}

// act3 [c(32)][n(512)][s(144)] -> xfc [n][c*144+s]
__global__ void repack_kernel()
{
    const int total = 512 * 4608;
    for (int idx = blockIdx.x * blockDim.x + threadIdx.x; idx < total;
         idx += gridDim.x * blockDim.x) {
        int n = idx / 4608;
        int k = idx - n * 4608;
        int c = k / 144;
        int s = k - c * 144;
        g_xfc[idx] = g_act3[(c * 512 + n) * 144 + s];
    }
}

__global__ void init_h_kernel(const float* __restrict__ states, float* __restrict__ h)
{
    int i = blockIdx.x * blockDim.x + threadIdx.x;
    if (i < 16 * 512) h[i] = states[i];
}

// ---------------------------------------------------------------------------
// One GRU step. warp-per-hidden-column j (512 warps across 64 blocks of 8).
// Each warp computes gh_r/gh_z/gh_n[j] for all 16 batch rows (k split over lanes).
// ---------------------------------------------------------------------------
__launch_bounds__(256)
__global__ void gru_step_kernel(const float* __restrict__ gi,
                                const float* __restrict__ w_hh,
                                const float* __restrict__ b_hh,
                                const float* __restrict__ masks,
                                const float* __restrict__ h_in,
                                float* __restrict__ h_out,
                                float* __restrict__ outs, int t)
{
    __shared__ float hs[16][512];
    const int tid = threadIdx.x;
    for (int i = tid; i < 16 * 512; i += 256) {
        int n = i >> 9;
        hs[n][i & 511] = h_in[i] * masks[t * 16 + n];
    }
    __syncthreads();

    const int warp = tid >> 5, lane = tid & 31;
    const int j = blockIdx.x * 8 + warp;   // 0..511 (hidden column)

    float ar[16], az[16], an[16];
#pragma unroll
    for (int n = 0; n < 16; n++) { ar[n] = 0.f; az[n] = 0.f; an[n] = 0.f; }

    const float* wr = w_hh + (size_t)j * 512;
    const float* wz = w_hh + (size_t)(512 + j) * 512;
    const float* wn = w_hh + (size_t)(1024 + j) * 512;

#pragma unroll
    for (int i = 0; i < 16; i++) {
        int k = i * 32 + lane;
        float vr = __ldg(&wr[k]);
        float vz = __ldg(&wz[k]);
        float vn = __ldg(&wn[k]);
#pragma unroll
        for (int n = 0; n < 16; n++) {
            float h = hs[n][k];
            ar[n] = fmaf(h, vr, ar[n]);
            az[n] = fmaf(h, vz, az[n]);
            an[n] = fmaf(h, vn, an[n]);
        }
    }
#pragma unroll
    for (int off = 16; off > 0; off >>= 1) {
#pragma unroll
        for (int n = 0; n < 16; n++) {
            ar[n] += __shfl_xor_sync(0xffffffffu, ar[n], off);
            az[n] += __shfl_xor_sync(0xffffffffu, az[n], off);
            an[n] += __shfl_xor_sync(0xffffffffu, an[n], off);
        }
    }
    if (lane < 16) {
        int n = lane;
        const float* gir = gi + (size_t)(t * 16 + n) * 1536;
        float r  = 1.f / (1.f + expf(-(gir[j]        + ar[n] + b_hh[j])));
        float z  = 1.f / (1.f + expf(-(gir[512 + j]  + az[n] + b_hh[512 + j])));
        float ng = tanhf(gir[1024 + j] + r * (an[n] + b_hh[1024 + j]));
        float hnew = (1.f - z) * ng + z * hs[n][j];
        h_out[n * 512 + j] = hnew;
        outs[(size_t)(t * 16 + n) * 512 + j] = hnew;
    }
}

// ---------------------------------------------------------------------------
// Heads: per row, 6 logits + value, log_softmax, entropy, gathered logp.
// ---------------------------------------------------------------------------
__launch_bounds__(128)
__global__ void heads_kernel(const float* __restrict__ outs,
                             const float* __restrict__ aw, const float* __restrict__ ab,
                             const float* __restrict__ cw, const float* __restrict__ cb,
                             const int* __restrict__ action,
                             float* __restrict__ out)
{
    const int row = blockIdx.x;
    const float* x = outs + (size_t)row * 512;
    float acc[7];
#pragma unroll
    for (int g = 0; g < 7; g++) acc[g] = 0.f;
    for (int k = threadIdx.x; k < 512; k += 128) {
        float xv = x[k];
#pragma unroll
        for (int g = 0; g < 6; g++) acc[g] = fmaf(xv, aw[g * 512 + k], acc[g]);
        acc[6] = fmaf(xv, cw[k], acc[6]);
    }
#pragma unroll
    for (int off = 16; off > 0; off >>= 1)
#pragma unroll
        for (int g = 0; g < 7; g++) acc[g] += __shfl_xor_sync(0xffffffffu, acc[g], off);

    __shared__ float red[4][7];
    int warp = threadIdx.x >> 5, lane = threadIdx.x & 31;
    if (lane == 0)
        for (int g = 0; g < 7; g++) red[warp][g] = acc[g];
    __syncthreads();

    if (threadIdx.x == 0) {
        float l[6], v;
        for (int g = 0; g < 6; g++)
            l[g] = red[0][g] + red[1][g] + red[2][g] + red[3][g] + ab[g];
        v = red[0][6] + red[1][6] + red[2][6] + red[3][6] + cb[0];

        float mx = l[0];
        for (int g = 1; g < 6; g++) mx = fmaxf(mx, l[g]);
        float se = 0.f;
        for (int g = 0; g < 6; g++) se += expf(l[g] - mx);
        float lse = logf(se) + mx;
        float ent = 0.f;
        for (int g = 0; g < 6; g++) { float lp = l[g] - lse; ent -= expf(lp) * lp; }

        int a = action[row];
        if (a < 0) a = 0;
        if (a > 5) a = 5;
        out[row]        = v;
        out[512 + row]  = l[a] - lse;
        out[1024 + row] = ent;
    }
}

__global__ void copy_states_kernel(const float* __restrict__ h, float* __restrict__ out)
{
    int i = blockIdx.x * blockDim.x + threadIdx.x;
    if (i < 16 * 512) out[1536 + i] = h[i];
}

// ---------------------------------------------------------------------------
extern "C" void kernel_launch(void* const* d_in, const int* in_sizes, int n_in,
                              void* d_out, int out_size)
{
    (void)in_sizes; (void)n_in; (void)out_size;
    const float* inputs = (const float*)d_in[0];
    const float* states = (const float*)d_in[1];
    const float* masks  = (const float*)d_in[2];
    const int*   action = (const int*)d_in[3];
    const float* c1w = (const float*)d_in[4];
    const float* c1b = (const float*)d_in[5];
    const float* c2w = (const float*)d_in[6];
    const float* c2b = (const float*)d_in[7];
    const float* c3w = (const float*)d_in[8];
    const float* c3b = (const float*)d_in[9];
    const float* fcw = (const float*)d_in[10];
    const float* fcb = (const float*)d_in[11];
    const float* wih = (const float*)d_in[12];
    const float* whh = (const float*)d_in[13];
    const float* bih = (const float*)d_in[14];
    const float* bhh = (const float*)d_in[15];
    const float* aw  = (const float*)d_in[16];
    const float* ab  = (const float*)d_in[17];
    const float* cw  = (const float*)d_in[18];
    const float* cb  = (const float*)d_in[19];
    float* out = (float*)d_out;

    float *act1, *act2, *act3, *part, *xb, *gi, *hbase, *outs;
    cudaGetSymbolAddress((void**)&act1,  g_act1);
    cudaGetSymbolAddress((void**)&act2,  g_act2);
    cudaGetSymbolAddress((void**)&act3,  g_act3);
    cudaGetSymbolAddress((void**)&part,  g_part);
    cudaGetSymbolAddress((void**)&xb,    g_x);
    cudaGetSymbolAddress((void**)&gi,    g_gi);
    cudaGetSymbolAddress((void**)&hbase, g_h);
    cudaGetSymbolAddress((void**)&outs,  g_outs);
    float* xfc;
    cudaGetSymbolAddress((void**)&xfc,   g_xfc);
    float* h0 = hbase;
    float* h1 = hbase + 16 * 512;

    // conv1: 4->32, 8x8 s4, input NCHW [512][4][124][124], N = 512*900 = 460800
    conv_gemm_kernel<4, 8, 124, 124, 30, 30, 4,
                     124 * 124, 4 * 124 * 124,
                     32, 256, 16, 8, 8, 128, true>
        <<<1800, 128>>>(c1w, c1b, inputs, act1);

    // conv2: 32->64, 4x4 s2, input [c][img][900], N = 512*196 = 100352
    conv_gemm_kernel<32, 4, 30, 30, 14, 14, 2,
                     512 * 900, 900,
                     64, 128, 16, 8, 8, 128, false>
        <<<784, 128>>>(c2w, c2b, act1, act2);

    // conv3: 64->32, 3x3 s1, input [c][img][196], N = 512*144 = 73728
    conv_gemm_kernel<64, 3, 14, 14, 12, 12, 1,
                     512 * 196, 196,
                     32, 256, 16, 8, 8, 128, false>
        <<<288, 128>>>(c3w, c3b, act2, act3);

    // repack conv3 output to fc input layout [n][4608]
    repack_kernel<<<4096, 256>>>();

    // fc: [512,4608] x [512,4608]^T, split-K = 12
    gemm_nt_splitk<128, 128, 16, 8, 8, 256>
        <<<dim3(4, 4, 12), 256>>>(xfc, fcw, part, 512, 512, 4608, 384);
    finalize_kernel<<<1024, 256>>>(part, 12, fcb, xb, 512 * 512, 512, 1);

    // gi: [512,512] x [1536,512]^T, split-K = 4
    gemm_nt_splitk<128, 128, 16, 8, 8, 256>
        <<<dim3(12, 4, 4), 256>>>(xb, wih, part, 512, 1536, 512, 128);
    finalize_kernel<<<3072, 256>>>(part, 4, bih, gi, 512 * 1536, 1536, 0);

    // GRU recurrence: 32 sequential steps, ping-pong hidden state
    init_h_kernel<<<32, 256>>>(states, h0);
    for (int t = 0; t < 32; t++) {
        float* hin  = (t & 1) ? h1 : h0;
        float* hout = (t & 1) ? h0 : h1;
        gru_step_kernel<<<64, 256>>>(gi, whh, bhh, masks, hin, hout, outs, t);
    }
    // after 32 steps the final hidden state is back in h0

    // heads + outputs
    heads_kernel<<<512, 128>>>(outs, aw, ab, cw, cb, action, out);
    copy_states_kernel<<<32, 256>>>(h0, out);
}

// round 4
// speedup vs baseline: 1.2873x; 1.2873x over previous
#include <cuda_runtime.h>
#include <math.h>

// ---------------------------------------------------------------------------
// Problem constants
//   T=32, N=16, TN=512, C=4, HW=124, A=6, H=512
//   conv1: 4->32, 8x8 s4 : 124 -> 30   (K=256,  N=512*900 =460800)
//   conv2: 32->64, 4x4 s2: 30 -> 14    (K=512,  N=512*196 =100352)
//   conv3: 64->32, 3x3 s1: 14 -> 12    (K=576,  N=512*144 = 73728)
//   fc: 4608 -> 512 ; GRU H=512 ; heads A=6 + value
// Output (9728 f32): value[512] | alp[512] | entropy[512] | states_out[16*512]
// ---------------------------------------------------------------------------

__device__ float g_act1[32 * 512 * 900];    // conv1 out [oc][img*900+s]
__device__ float g_act2[64 * 512 * 196];    // conv2 out [oc][img*196+s]
__device__ float g_xfc[512 * 4608];         // conv3 out in fc layout [img][c*144+s]
__device__ float g_part[8 * 512 * 1536];    // split-K partials (fc / gi)
__device__ float g_x[512 * 512];            // fc output (relu)
__device__ float g_gi[512 * 1536];          // input gates [t*16+n][1536]
__device__ float g_h[2][16 * 512];          // GRU hidden ping-pong
__device__ float g_outs[512 * 512];         // GRU outputs [t*16+n][512]
__device__ int   g_barrier_i;

// ------------------------------ tf32 helpers -------------------------------
__device__ __forceinline__ unsigned f2tf32(float f) {
    unsigned u;
    asm("cvt.rna.tf32.f32 %0, %1;" : "=r"(u) : "f"(f));
    return u;
}

__device__ __forceinline__ void mma_tf32(float& c0, float& c1, float& c2, float& c3,
                                         unsigned a0, unsigned a1, unsigned a2, unsigned a3,
                                         unsigned b0, unsigned b1)
{
    asm volatile(
        "mma.sync.aligned.m16n8k8.row.col.f32.tf32.tf32.f32 "
        "{%0,%1,%2,%3},{%4,%5,%6,%7},{%8,%9},{%0,%1,%2,%3};"
        : "+f"(c0), "+f"(c1), "+f"(c2), "+f"(c3)
        : "r"(a0), "r"(a1), "r"(a2), "r"(a3), "r"(b0), "r"(b1));
}

// ---------------------------------------------------------------------------
// TF32 implicit-im2col conv GEMM.
//   out[m][n] = relu(sum_k W[m][k]*col[k][n] + b[m]),  m = OC row, n = (img, oy, ox)
//   BM == OC, BN = 256, BK = 32. 256 threads, 8 warps, warp tile 32 x WN.
//   Fragment layouts: mma.m16n8k8 tf32 (Ampere-standard).
// ---------------------------------------------------------------------------
template<int C, int KK, int IW, int OW, int STRIDE,
         int CH_STRIDE, int IMG_STRIDE,
         int BM, bool SCALE, bool XFC_OUT>
__launch_bounds__(256)
__global__ void conv_mma_kernel(const float* __restrict__ W,
                                const float* __restrict__ bias,
                                const float* __restrict__ in,
                                float* __restrict__ out)
{
    constexpr int K     = C * KK * KK;
    constexpr int SPER  = OW * OW;
    constexpr int NTOT  = 512 * SPER;
    constexpr int BN    = 256;
    constexpr int BK    = 32;
    constexpr int WARPS_M = BM / 32;
    constexpr int WARPS_N = 8 / WARPS_M;
    constexpr int WN      = BN / WARPS_N;
    constexpr int NFRAG   = WN / 8;

    __shared__ unsigned As[BM][36];   // [m][k] tf32 bits
    __shared__ unsigned Bs[BN][36];   // [n][k] tf32 bits
    __shared__ int nb[BN];

    const int tid  = threadIdx.x;
    const int bn0  = blockIdx.x * BN;
    const int warp = tid >> 5, lane = tid & 31;
    const int g = lane >> 2, t4 = lane & 3;
    const int warp_m = warp / WARPS_N, warp_n = warp % WARPS_N;
    const int m_base = warp_m * 32, n_base = warp_n * WN;

    for (int i = tid; i < BN; i += 256) {
        int ng  = bn0 + i;
        int img = ng / SPER;
        int r   = ng - img * SPER;
        int oy  = r / OW;
        int ox  = r - oy * OW;
        nb[i] = img * IMG_STRIDE + oy * STRIDE * IW + ox * STRIDE;
    }
    __syncthreads();

    float acc[2][NFRAG][4];
#pragma unroll
    for (int mt = 0; mt < 2; mt++)
#pragma unroll
        for (int nf = 0; nf < NFRAG; nf++)
#pragma unroll
            for (int q = 0; q < 4; q++) acc[mt][nf][q] = 0.f;

    for (int k0 = 0; k0 < K; k0 += BK) {
        // A tile (weights), coalesced per m-row
        for (int idx = tid; idx < BM * BK; idx += 256) {
            int m = idx >> 5, kk = idx & 31;
            As[m][kk] = f2tf32(W[m * K + k0 + kk]);
        }
        // B tile: implicit im2col gather (n fastest -> coalesced gmem)
        for (int idx = tid; idx < BK * BN; idx += 256) {
            int kk = idx >> 8, nn = idx & (BN - 1);
            int kg = k0 + kk;
            int c  = kg / (KK * KK);
            int r  = kg - c * (KK * KK);
            int ky = r / KK, kx = r - ky * KK;
            float v = __ldg(&in[nb[nn] + c * CH_STRIDE + ky * IW + kx]);
            Bs[nn][kk] = f2tf32(SCALE ? v * (1.0f / 255.0f) : v);
        }
        __syncthreads();

#pragma unroll
        for (int ks = 0; ks < 4; ks++) {
            const int kl = ks * 8;
            unsigned a[2][4];
#pragma unroll
            for (int mt = 0; mt < 2; mt++) {
                int mr = m_base + mt * 16 + g;
                a[mt][0] = As[mr][kl + t4];
                a[mt][1] = As[mr + 8][kl + t4];
                a[mt][2] = As[mr][kl + t4 + 4];
                a[mt][3] = As[mr + 8][kl + t4 + 4];
            }
#pragma unroll
            for (int nf = 0; nf < NFRAG; nf++) {
                int nr = n_base + nf * 8 + g;
                unsigned b0 = Bs[nr][kl + t4];
                unsigned b1 = Bs[nr][kl + t4 + 4];
#pragma unroll
                for (int mt = 0; mt < 2; mt++)
                    mma_tf32(acc[mt][nf][0], acc[mt][nf][1], acc[mt][nf][2], acc[mt][nf][3],
                             a[mt][0], a[mt][1], a[mt][2], a[mt][3], b0, b1);
            }
        }
        __syncthreads();
    }

    // epilogue
#pragma unroll
    for (int mt = 0; mt < 2; mt++) {
        int m0g = m_base + mt * 16 + g;
        float b0 = bias[m0g];
        float b1 = bias[m0g + 8];
#pragma unroll
        for (int nf = 0; nf < NFRAG; nf++) {
            int n = bn0 + n_base + nf * 8 + t4 * 2;
            float v00 = fmaxf(acc[mt][nf][0] + b0, 0.f);
            float v01 = fmaxf(acc[mt][nf][1] + b0, 0.f);
            float v10 = fmaxf(acc[mt][nf][2] + b1, 0.f);
            float v11 = fmaxf(acc[mt][nf][3] + b1, 0.f);
            if (XFC_OUT) {
                int img = n / SPER, s = n - img * SPER;
                out[img * (32 * SPER) + m0g * SPER + s]           = v00;
                out[img * (32 * SPER) + m0g * SPER + s + 1]       = v01;
                out[img * (32 * SPER) + (m0g + 8) * SPER + s]     = v10;
                out[img * (32 * SPER) + (m0g + 8) * SPER + s + 1] = v11;
            } else {
                out[(size_t)m0g * NTOT + n]           = v00;
                out[(size_t)m0g * NTOT + n + 1]       = v01;
                out[(size_t)(m0g + 8) * NTOT + n]     = v10;
                out[(size_t)(m0g + 8) * NTOT + n + 1] = v11;
            }
        }
    }
}

// ---------------------------------------------------------------------------
// TF32 NT GEMM with split-K: partial[z] = A[M][K] * B[N][K]^T over k slice.
// ---------------------------------------------------------------------------
template<int BM, int BN>
__launch_bounds__(256)
__global__ void gemm_nt_mma(const float* __restrict__ A, const float* __restrict__ B,
                            float* __restrict__ partial, int M, int N, int K, int kps)
{
    constexpr int BK = 32;
    constexpr int WARPS_M = BM / 32;
    constexpr int WARPS_N = 8 / WARPS_M;
    constexpr int WN      = BN / WARPS_N;
    constexpr int NFRAG   = WN / 8;

    __shared__ unsigned As[BM][36];
    __shared__ unsigned Bs[BN][36];

    const int tid  = threadIdx.x;
    const int m0   = blockIdx.y * BM, n0 = blockIdx.x * BN;
    const int kbeg = blockIdx.z * kps;
    const int warp = tid >> 5, lane = tid & 31;
    const int g = lane >> 2, t4 = lane & 3;
    const int warp_m = warp / WARPS_N, warp_n = warp % WARPS_N;
    const int m_base = warp_m * 32, n_base = warp_n * WN;

    float acc[2][NFRAG][4];
#pragma unroll
    for (int mt = 0; mt < 2; mt++)
#pragma unroll
        for (int nf = 0; nf < NFRAG; nf++)
#pragma unroll
            for (int q = 0; q < 4; q++) acc[mt][nf][q] = 0.f;

    for (int k0 = kbeg; k0 < kbeg + kps; k0 += BK) {
        for (int idx = tid; idx < BM * BK; idx += 256) {
            int m = idx >> 5, kk = idx & 31;
            As[m][kk] = f2tf32(A[(size_t)(m0 + m) * K + k0 + kk]);
        }
        for (int idx = tid; idx < BN * BK; idx += 256) {
            int n = idx >> 5, kk = idx & 31;
            Bs[n][kk] = f2tf32(B[(size_t)(n0 + n) * K + k0 + kk]);
        }
        __syncthreads();

#pragma unroll
        for (int ks = 0; ks < 4; ks++) {
            const int kl = ks * 8;
            unsigned a[2][4];
#pragma unroll
            for (int mt = 0; mt < 2; mt++) {
                int mr = m_base + mt * 16 + g;
                a[mt][0] = As[mr][kl + t4];
                a[mt][1] = As[mr + 8][kl + t4];
                a[mt][2] = As[mr][kl + t4 + 4];
                a[mt][3] = As[mr + 8][kl + t4 + 4];
            }
#pragma unroll
            for (int nf = 0; nf < NFRAG; nf++) {
                int nr = n_base + nf * 8 + g;
                unsigned b0 = Bs[nr][kl + t4];
                unsigned b1 = Bs[nr][kl + t4 + 4];
#pragma unroll
                for (int mt = 0; mt < 2; mt++)
                    mma_tf32(acc[mt][nf][0], acc[mt][nf][1], acc[mt][nf][2], acc[mt][nf][3],
                             a[mt][0], a[mt][1], a[mt][2], a[mt][3], b0, b1);
            }
        }
        __syncthreads();
    }

    float* p = partial + (size_t)blockIdx.z * M * N;
#pragma unroll
    for (int mt = 0; mt < 2; mt++) {
        int m = m0 + m_base + mt * 16 + g;
#pragma unroll
        for (int nf = 0; nf < NFRAG; nf++) {
            int n = n0 + n_base + nf * 8 + t4 * 2;
            p[(size_t)m * N + n]           = acc[mt][nf][0];
            p[(size_t)m * N + n + 1]       = acc[mt][nf][1];
            p[(size_t)(m + 8) * N + n]     = acc[mt][nf][2];
            p[(size_t)(m + 8) * N + n + 1] = acc[mt][nf][3];
        }
    }
}

__global__ void finalize_kernel(const float* __restrict__ partial, int S,
                                const float* __restrict__ bias,
                                float* __restrict__ out, int MN, int N, int relu)
{
    for (int i = blockIdx.x * blockDim.x + threadIdx.x; i < MN;
         i += gridDim.x * blockDim.x) {
        float v = 0.f;
        for (int s = 0; s < S; s++) v += partial[(size_t)s * MN + i];
        v += bias[i % N];
        out[i] = relu ? fmaxf(v, 0.f) : v;
    }
}

__global__ void zero_barrier_kernel() { g_barrier_i = 0; }

// ---------------------------------------------------------------------------
// Persistent GRU: 128 blocks x 128 threads. warp -> hidden column j.
// w_hh rows held in registers; per-step grid barrier via atomic counter.
// h ping-pong through L2 (__ldcg/__stcg) since L1 is not coherent.
// ---------------------------------------------------------------------------
__launch_bounds__(128)
__global__ void gru_persistent_kernel(const float* __restrict__ gi,
                                      const float* __restrict__ w_hh,
                                      const float* __restrict__ b_hh,
                                      const float* __restrict__ masks,
                                      const float* __restrict__ states,
                                      float* __restrict__ h0,
                                      float* __restrict__ h1,
                                      float* __restrict__ outs)
{
    __shared__ float hs[16][512];
    const int tid = threadIdx.x;
    const int warp = tid >> 5, lane = tid & 31;
    const int j = blockIdx.x * 4 + warp;    // 0..511

    float wr[16], wz[16], wn[16];
    const float* wrp = w_hh + (size_t)j * 512;
    const float* wzp = w_hh + (size_t)(512 + j) * 512;
    const float* wnp = w_hh + (size_t)(1024 + j) * 512;
#pragma unroll
    for (int i = 0; i < 16; i++) {
        int k = i * 32 + lane;
        wr[i] = __ldg(&wrp[k]);
        wz[i] = __ldg(&wzp[k]);
        wn[i] = __ldg(&wnp[k]);
    }
    const float bjr = b_hh[j], bjz = b_hh[512 + j], bjn = b_hh[1024 + j];

    for (int t = 0; t < 32; t++) {
        const float* hin = (t == 0) ? states : (((t & 1) == 1) ? h0 : h1);
        float* hout = (t & 1) ? h1 : h0;

        for (int i = tid; i < 16 * 512; i += 128) {
            int n = i >> 9;
            hs[n][i & 511] = __ldcg(&hin[i]) * masks[t * 16 + n];
        }
        __syncthreads();

        float ar[16], az[16], an[16];
#pragma unroll
        for (int n = 0; n < 16; n++) { ar[n] = 0.f; az[n] = 0.f; an[n] = 0.f; }

#pragma unroll
        for (int i = 0; i < 16; i++) {
            int k = i * 32 + lane;
            float vr = wr[i], vz = wz[i], vn = wn[i];
#pragma unroll
            for (int n = 0; n < 16; n++) {
                float h = hs[n][k];
                ar[n] = fmaf(h, vr, ar[n]);
                az[n] = fmaf(h, vz, az[n]);
                an[n] = fmaf(h, vn, an[n]);
            }
        }
#pragma unroll
        for (int off = 16; off > 0; off >>= 1) {
#pragma unroll
            for (int n = 0; n < 16; n++) {
                ar[n] += __shfl_xor_sync(0xffffffffu, ar[n], off);
                az[n] += __shfl_xor_sync(0xffffffffu, az[n], off);
                an[n] += __shfl_xor_sync(0xffffffffu, an[n], off);
            }
        }
        if (lane < 16) {
            int n = lane;
            const float* gir = gi + (size_t)(t * 16 + n) * 1536;
            float r  = 1.f / (1.f + expf(-(gir[j]        + ar[n] + bjr)));
            float z  = 1.f / (1.f + expf(-(gir[512 + j]  + az[n] + bjz)));
            float ng = tanhf(gir[1024 + j] + r * (an[n] + bjn));
            float hnew = (1.f - z) * ng + z * hs[n][j];
            __stcg(&hout[n * 512 + j], hnew);
            outs[(size_t)(t * 16 + n) * 512 + j] = hnew;
        }

        if (t < 31) {
            __syncthreads();
            __threadfence();
            if (tid == 0) {
                atomicAdd(&g_barrier_i, 1);
                int target = 128 * (t + 1);
                while (*((volatile int*)&g_barrier_i) < target) __nanosleep(32);
            }
            __syncthreads();
        }
    }
}

// ---------------------------------------------------------------------------
// Heads: per row, 6 logits + value, log_softmax, entropy, gathered logp.
// ---------------------------------------------------------------------------
__launch_bounds__(128)
__global__ void heads_kernel(const float* __restrict__ outs,
                             const float* __restrict__ aw, const float* __restrict__ ab,
                             const float* __restrict__ cw, const float* __restrict__ cb,
                             const int* __restrict__ action,
                             float* __restrict__ out)
{
    const int row = blockIdx.x;
    const float* x = outs + (size_t)row * 512;
    float acc[7];
#pragma unroll
    for (int g = 0; g < 7; g++) acc[g] = 0.f;
    for (int k = threadIdx.x; k < 512; k += 128) {
        float xv = x[k];
#pragma unroll
        for (int g = 0; g < 6; g++) acc[g] = fmaf(xv, aw[g * 512 + k], acc[g]);
        acc[6] = fmaf(xv, cw[k], acc[6]);
    }
#pragma unroll
    for (int off = 16; off > 0; off >>= 1)
#pragma unroll
        for (int g = 0; g < 7; g++) acc[g] += __shfl_xor_sync(0xffffffffu, acc[g], off);

    __shared__ float red[4][7];
    int warp = threadIdx.x >> 5, lane = threadIdx.x & 31;
    if (lane == 0)
        for (int g = 0; g < 7; g++) red[warp][g] = acc[g];
    __syncthreads();

    if (threadIdx.x == 0) {
        float l[6], v;
        for (int g = 0; g < 6; g++)
            l[g] = red[0][g] + red[1][g] + red[2][g] + red[3][g] + ab[g];
        v = red[0][6] + red[1][6] + red[2][6] + red[3][6] + cb[0];

        float mx = l[0];
        for (int g = 1; g < 6; g++) mx = fmaxf(mx, l[g]);
        float se = 0.f;
        for (int g = 0; g < 6; g++) se += expf(l[g] - mx);
        float lse = logf(se) + mx;
        float ent = 0.f;
        for (int g = 0; g < 6; g++) { float lp = l[g] - lse; ent -= expf(lp) * lp; }

        int a = action[row];
        if (a < 0) a = 0;
        if (a > 5) a = 5;
        out[row]        = v;
        out[512 + row]  = l[a] - lse;
        out[1024 + row] = ent;
    }
}

__global__ void copy_states_kernel(const float* __restrict__ h, float* __restrict__ out)
{
    int i = blockIdx.x * blockDim.x + threadIdx.x;
    if (i < 16 * 512) out[1536 + i] = h[i];
}

// ---------------------------------------------------------------------------
extern "C" void kernel_launch(void* const* d_in, const int* in_sizes, int n_in,
                              void* d_out, int out_size)
{
    (void)in_sizes; (void)n_in; (void)out_size;
    const float* inputs = (const float*)d_in[0];
    const float* states = (const float*)d_in[1];
    const float* masks  = (const float*)d_in[2];
    const int*   action = (const int*)d_in[3];
    const float* c1w = (const float*)d_in[4];
    const float* c1b = (const float*)d_in[5];
    const float* c2w = (const float*)d_in[6];
    const float* c2b = (const float*)d_in[7];
    const float* c3w = (const float*)d_in[8];
    const float* c3b = (const float*)d_in[9];
    const float* fcw = (const float*)d_in[10];
    const float* fcb = (const float*)d_in[11];
    const float* wih = (const float*)d_in[12];
    const float* whh = (const float*)d_in[13];
    const float* bih = (const float*)d_in[14];
    const float* bhh = (const float*)d_in[15];
    const float* aw  = (const float*)d_in[16];
    const float* ab  = (const float*)d_in[17];
    const float* cw  = (const float*)d_in[18];
    const float* cb  = (const float*)d_in[19];
    float* out = (float*)d_out;

    float *act1, *act2, *xfc, *part, *xb, *gi, *hbase, *outs;
    cudaGetSymbolAddress((void**)&act1,  g_act1);
    cudaGetSymbolAddress((void**)&act2,  g_act2);
    cudaGetSymbolAddress((void**)&xfc,   g_xfc);
    cudaGetSymbolAddress((void**)&part,  g_part);
    cudaGetSymbolAddress((void**)&xb,    g_x);
    cudaGetSymbolAddress((void**)&gi,    g_gi);
    cudaGetSymbolAddress((void**)&hbase, g_h);
    cudaGetSymbolAddress((void**)&outs,  g_outs);
    float* h0 = hbase;
    float* h1 = hbase + 16 * 512;

    // conv1: 4->32, 8x8 s4, NCHW [512][4][124][124] -> act1 [32][460800]
    conv_mma_kernel<4, 8, 124, 30, 4, 124 * 124, 4 * 124 * 124, 32, true, false>
        <<<1800, 256>>>(c1w, c1b, inputs, act1);

    // conv2: 32->64, 4x4 s2, act1 [c][img*900+s] -> act2 [64][100352]
    conv_mma_kernel<32, 4, 30, 14, 2, 512 * 900, 900, 64, false, false>
        <<<392, 256>>>(c2w, c2b, act1, act2);

    // conv3: 64->32, 3x3 s1, act2 [c][img*196+s] -> xfc [img][c*144+s] (direct)
    conv_mma_kernel<64, 3, 14, 12, 1, 512 * 196, 196, 32, false, true>
        <<<288, 256>>>(c3w, c3b, act2, xfc);

    // fc: [512,4608] x [512,4608]^T, split-K 8 (kps=576)
    gemm_nt_mma<64, 256><<<dim3(2, 8, 8), 256>>>(xfc, fcw, part, 512, 512, 4608, 576);
    finalize_kernel<<<1024, 256>>>(part, 8, fcb, xb, 512 * 512, 512, 1);

    // gi: [512,512] x [1536,512]^T, split-K 2 (kps=256)
    gemm_nt_mma<64, 256><<<dim3(6, 8, 2), 256>>>(xb, wih, part, 512, 1536, 512, 256);
    finalize_kernel<<<3072, 256>>>(part, 2, bih, gi, 512 * 1536, 1536, 0);

    // GRU recurrence: single persistent kernel with grid-wide step barrier
    zero_barrier_kernel<<<1, 1>>>();
    gru_persistent_kernel<<<128, 128>>>(gi, whh, bhh, masks, states, h0, h1, outs);

    // heads + outputs (final hidden state is in h1: t=31 writes buf[31&1])
    heads_kernel<<<512, 128>>>(outs, aw, ab, cw, cb, action, out);
    copy_states_kernel<<<32, 256>>>(h1, out);
}

// round 5
// speedup vs baseline: 1.2940x; 1.0052x over previous
#include <cuda_runtime.h>
#include <math.h>

// ---------------------------------------------------------------------------
// Problem constants
//   T=32, N=16, TN=512, C=4, HW=124, A=6, H=512
//   conv1: 4->32, 8x8 s4 : 124 -> 30   (K=256,  N=512*900 =460800)
//   conv2: 32->64, 4x4 s2: 30 -> 14    (K=512,  N=512*196 =100352)
//   conv3: 64->32, 3x3 s1: 14 -> 12    (K=576,  N=512*144 = 73728)
//   fc: 4608 -> 512 ; GRU H=512 ; heads A=6 + value
// Output (9728 f32): value[512] | alp[512] | entropy[512] | states_out[16*512]
// ---------------------------------------------------------------------------

__device__ float g_act1[32 * 512 * 900];    // conv1 out [oc][img*900+s]
__device__ float g_act2[64 * 512 * 196];    // conv2 out [oc][img*196+s]
__device__ float g_xfc[512 * 4608];         // conv3 out in fc layout [img][c*144+s]
__device__ float g_part[8 * 512 * 1536];    // split-K partials (fc / gi)
__device__ float g_x[512 * 512];            // fc output (relu)
__device__ float g_gi[512 * 1536];          // input gates [t*16+n][1536]
__device__ float g_h[2][16 * 512];          // GRU hidden ping-pong
__device__ float g_outs[512 * 512];         // GRU outputs [t*16+n][512]
__device__ int   g_barrier_i;

// ------------------------------ tf32 helpers -------------------------------
__device__ __forceinline__ unsigned f2tf32(float f) {
    unsigned u;
    asm("cvt.rna.tf32.f32 %0, %1;" : "=r"(u) : "f"(f));
    return u;
}

__device__ __forceinline__ void mma_tf32(float& c0, float& c1, float& c2, float& c3,
                                         unsigned a0, unsigned a1, unsigned a2, unsigned a3,
                                         unsigned b0, unsigned b1)
{
    asm volatile(
        "mma.sync.aligned.m16n8k8.row.col.f32.tf32.tf32.f32 "
        "{%0,%1,%2,%3},{%4,%5,%6,%7},{%8,%9},{%0,%1,%2,%3};"
        : "+f"(c0), "+f"(c1), "+f"(c2), "+f"(c3)
        : "r"(a0), "r"(a1), "r"(a2), "r"(a3), "r"(b0), "r"(b1));
}

// ---------------------------------------------------------------------------
// TF32 implicit-im2col conv GEMM.
//   out[m][n] = relu(sum_k W[m][k]*col[k][n] + b[m]),  m = OC row, n = (img, oy, ox)
//   BM == OC, BN = 256, BK = 32. 256 threads, 8 warps, warp tile 32 x WN.
//   Fragment layouts: mma.m16n8k8 tf32 (Ampere-standard).
// ---------------------------------------------------------------------------
template<int C, int KK, int IW, int OW, int STRIDE,
         int CH_STRIDE, int IMG_STRIDE,
         int BM, bool SCALE, bool XFC_OUT>
__launch_bounds__(256)
__global__ void conv_mma_kernel(const float* __restrict__ W,
                                const float* __restrict__ bias,
                                const float* __restrict__ in,
                                float* __restrict__ out)
{
    constexpr int K     = C * KK * KK;
    constexpr int SPER  = OW * OW;
    constexpr int NTOT  = 512 * SPER;
    constexpr int BN    = 256;
    constexpr int BK    = 32;
    constexpr int WARPS_M = BM / 32;
    constexpr int WARPS_N = 8 / WARPS_M;
    constexpr int WN      = BN / WARPS_N;
    constexpr int NFRAG   = WN / 8;

    __shared__ unsigned As[BM][36];   // [m][k] tf32 bits
    __shared__ unsigned Bs[BN][36];   // [n][k] tf32 bits
    __shared__ int nb[BN];

    const int tid  = threadIdx.x;
    const int bn0  = blockIdx.x * BN;
    const int warp = tid >> 5, lane = tid & 31;
    const int g = lane >> 2, t4 = lane & 3;
    const int warp_m = warp / WARPS_N, warp_n = warp % WARPS_N;
    const int m_base = warp_m * 32, n_base = warp_n * WN;

    for (int i = tid; i < BN; i += 256) {
        int ng  = bn0 + i;
        int img = ng / SPER;
        int r   = ng - img * SPER;
        int oy  = r / OW;
        int ox  = r - oy * OW;
        nb[i] = img * IMG_STRIDE + oy * STRIDE * IW + ox * STRIDE;
    }
    __syncthreads();

    float acc[2][NFRAG][4];
#pragma unroll
    for (int mt = 0; mt < 2; mt++)
#pragma unroll
        for (int nf = 0; nf < NFRAG; nf++)
#pragma unroll
            for (int q = 0; q < 4; q++) acc[mt][nf][q] = 0.f;

    for (int k0 = 0; k0 < K; k0 += BK) {
        // A tile (weights), coalesced per m-row
        for (int idx = tid; idx < BM * BK; idx += 256) {
            int m = idx >> 5, kk = idx & 31;
            As[m][kk] = f2tf32(W[m * K + k0 + kk]);
        }
        // B tile: implicit im2col gather (n fastest -> coalesced gmem)
        for (int idx = tid; idx < BK * BN; idx += 256) {
            int kk = idx >> 8, nn = idx & (BN - 1);
            int kg = k0 + kk;
            int c  = kg / (KK * KK);
            int r  = kg - c * (KK * KK);
            int ky = r / KK, kx = r - ky * KK;
            float v = __ldg(&in[nb[nn] + c * CH_STRIDE + ky * IW + kx]);
            Bs[nn][kk] = f2tf32(SCALE ? v * (1.0f / 255.0f) : v);
        }
        __syncthreads();

#pragma unroll
        for (int ks = 0; ks < 4; ks++) {
            const int kl = ks * 8;
            unsigned a[2][4];
#pragma unroll
            for (int mt = 0; mt < 2; mt++) {
                int mr = m_base + mt * 16 + g;
                a[mt][0] = As[mr][kl + t4];
                a[mt][1] = As[mr + 8][kl + t4];
                a[mt][2] = As[mr][kl + t4 + 4];
                a[mt][3] = As[mr + 8][kl + t4 + 4];
            }
#pragma unroll
            for (int nf = 0; nf < NFRAG; nf++) {
                int nr = n_base + nf * 8 + g;
                unsigned b0 = Bs[nr][kl + t4];
                unsigned b1 = Bs[nr][kl + t4 + 4];
#pragma unroll
                for (int mt = 0; mt < 2; mt++)
                    mma_tf32(acc[mt][nf][0], acc[mt][nf][1], acc[mt][nf][2], acc[mt][nf][3],
                             a[mt][0], a[mt][1], a[mt][2], a[mt][3], b0, b1);
            }
        }
        __syncthreads();
    }

    // epilogue
#pragma unroll
    for (int mt = 0; mt < 2; mt++) {
        int m0g = m_base + mt * 16 + g;
        float b0 = bias[m0g];
        float b1 = bias[m0g + 8];
#pragma unroll
        for (int nf = 0; nf < NFRAG; nf++) {
            int n = bn0 + n_base + nf * 8 + t4 * 2;
            float v00 = fmaxf(acc[mt][nf][0] + b0, 0.f);
            float v01 = fmaxf(acc[mt][nf][1] + b0, 0.f);
            float v10 = fmaxf(acc[mt][nf][2] + b1, 0.f);
            float v11 = fmaxf(acc[mt][nf][3] + b1, 0.f);
            if (XFC_OUT) {
                int img = n / SPER, s = n - img * SPER;
                out[img * (32 * SPER) + m0g * SPER + s]           = v00;
                out[img * (32 * SPER) + m0g * SPER + s + 1]       = v01;
                out[img * (32 * SPER) + (m0g + 8) * SPER + s]     = v10;
                out[img * (32 * SPER) + (m0g + 8) * SPER + s + 1] = v11;
            } else {
                out[(size_t)m0g * NTOT + n]           = v00;
                out[(size_t)m0g * NTOT + n + 1]       = v01;
                out[(size_t)(m0g + 8) * NTOT + n]     = v10;
                out[(size_t)(m0g + 8) * NTOT + n + 1] = v11;
            }
        }
    }
}

// ---------------------------------------------------------------------------
// TF32 NT GEMM with split-K: partial[z] = A[M][K] * B[N][K]^T over k slice.
// ---------------------------------------------------------------------------
template<int BM, int BN>
__launch_bounds__(256)
__global__ void gemm_nt_mma(const float* __restrict__ A, const float* __restrict__ B,
                            float* __restrict__ partial, int M, int N, int K, int kps)
{
    constexpr int BK = 32;
    constexpr int WARPS_M = BM / 32;
    constexpr int WARPS_N = 8 / WARPS_M;
    constexpr int WN      = BN / WARPS_N;
    constexpr int NFRAG   = WN / 8;

    __shared__ unsigned As[BM][36];
    __shared__ unsigned Bs[BN][36];

    const int tid  = threadIdx.x;
    const int m0   = blockIdx.y * BM, n0 = blockIdx.x * BN;
    const int kbeg = blockIdx.z * kps;
    const int warp = tid >> 5, lane = tid & 31;
    const int g = lane >> 2, t4 = lane & 3;
    const int warp_m = warp / WARPS_N, warp_n = warp % WARPS_N;
    const int m_base = warp_m * 32, n_base = warp_n * WN;

    float acc[2][NFRAG][4];
#pragma unroll
    for (int mt = 0; mt < 2; mt++)
#pragma unroll
        for (int nf = 0; nf < NFRAG; nf++)
#pragma unroll
            for (int q = 0; q < 4; q++) acc[mt][nf][q] = 0.f;

    for (int k0 = kbeg; k0 < kbeg + kps; k0 += BK) {
        for (int idx = tid; idx < BM * BK; idx += 256) {
            int m = idx >> 5, kk = idx & 31;
            As[m][kk] = f2tf32(A[(size_t)(m0 + m) * K + k0 + kk]);
        }
        for (int idx = tid; idx < BN * BK; idx += 256) {
            int n = idx >> 5, kk = idx & 31;
            Bs[n][kk] = f2tf32(B[(size_t)(n0 + n) * K + k0 + kk]);
        }
        __syncthreads();

#pragma unroll
        for (int ks = 0; ks < 4; ks++) {
            const int kl = ks * 8;
            unsigned a[2][4];
#pragma unroll
            for (int mt = 0; mt < 2; mt++) {
                int mr = m_base + mt * 16 + g;
                a[mt][0] = As[mr][kl + t4];
                a[mt][1] = As[mr + 8][kl + t4];
                a[mt][2] = As[mr][kl + t4 + 4];
                a[mt][3] = As[mr + 8][kl + t4 + 4];
            }
#pragma unroll
            for (int nf = 0; nf < NFRAG; nf++) {
                int nr = n_base + nf * 8 + g;
                unsigned b0 = Bs[nr][kl + t4];
                unsigned b1 = Bs[nr][kl + t4 + 4];
#pragma unroll
                for (int mt = 0; mt < 2; mt++)
                    mma_tf32(acc[mt][nf][0], acc[mt][nf][1], acc[mt][nf][2], acc[mt][nf][3],
                             a[mt][0], a[mt][1], a[mt][2], a[mt][3], b0, b1);
            }
        }
        __syncthreads();
    }

    float* p = partial + (size_t)blockIdx.z * M * N;
#pragma unroll
    for (int mt = 0; mt < 2; mt++) {
        int m = m0 + m_base + mt * 16 + g;
#pragma unroll
        for (int nf = 0; nf < NFRAG; nf++) {
            int n = n0 + n_base + nf * 8 + t4 * 2;
            p[(size_t)m * N + n]           = acc[mt][nf][0];
            p[(size_t)m * N + n + 1]       = acc[mt][nf][1];
            p[(size_t)(m + 8) * N + n]     = acc[mt][nf][2];
            p[(size_t)(m + 8) * N + n + 1] = acc[mt][nf][3];
        }
    }
}

__global__ void finalize_kernel(const float* __restrict__ partial, int S,
                                const float* __restrict__ bias,
                                float* __restrict__ out, int MN, int N, int relu)
{
    for (int i = blockIdx.x * blockDim.x + threadIdx.x; i < MN;
         i += gridDim.x * blockDim.x) {
        float v = 0.f;
        for (int s = 0; s < S; s++) v += partial[(size_t)s * MN + i];
        v += bias[i % N];
        out[i] = relu ? fmaxf(v, 0.f) : v;
    }
}

__global__ void zero_barrier_kernel() { g_barrier_i = 0; }

// ---------------------------------------------------------------------------
// Persistent GRU: 128 blocks x 128 threads. warp -> hidden column j.
// w_hh rows held in registers; per-step grid barrier via atomic counter.
// h ping-pong through L2 (__ldcg/__stcg) since L1 is not coherent.
// ---------------------------------------------------------------------------
__launch_bounds__(128)
__global__ void gru_persistent_kernel(const float* __restrict__ gi,
                                      const float* __restrict__ w_hh,
                                      const float* __restrict__ b_hh,
                                      const float* __restrict__ masks,
                                      const float* __restrict__ states,
                                      float* __restrict__ h0,
                                      float* __restrict__ h1,
                                      float* __restrict__ outs)
{
    __shared__ float hs[16][512];
    const int tid = threadIdx.x;
    const int warp = tid >> 5, lane = tid & 31;
    const int j = blockIdx.x * 4 + warp;    // 0..511

    float wr[16], wz[16], wn[16];
    const float* wrp = w_hh + (size_t)j * 512;
    const float* wzp = w_hh + (size_t)(512 + j) * 512;
    const float* wnp = w_hh + (size_t)(1024 + j) * 512;
#pragma unroll
    for (int i = 0; i < 16; i++) {
        int k = i * 32 + lane;
        wr[i] = __ldg(&wrp[k]);
        wz[i] = __ldg(&wzp[k]);
        wn[i] = __ldg(&wnp[k]);
    }
    const float bjr = b_hh[j], bjz = b_hh[512 + j], bjn = b_hh[1024 + j];

    for (int t = 0; t < 32; t++) {
        const float* hin = (t == 0) ? states : (((t & 1) == 1) ? h0 : h1);
        float* hout = (t & 1) ? h1 : h0;

        for (int i = tid; i < 16 * 512; i += 128) {
            int n = i >> 9;
            hs[n][i & 511] = __ldcg(&hin[i]) * masks[t * 16 + n];
        }
        __syncthreads();

        float ar[16], az[16], an[16];
#pragma unroll
        for (int n = 0; n < 16; n++) { ar[n] = 0.f; az[n] = 0.f; an[n] = 0.f; }

#pragma unroll
        for (int i = 0; i < 16; i++) {
            int k = i * 32 + lane;
            float vr = wr[i], vz = wz[i], vn = wn[i];
#pragma unroll
            for (int n = 0; n < 16; n++) {
                float h = hs[n][k];
                ar[n] = fmaf(h, vr, ar[n]);
                az[n] = fmaf(h, vz, az[n]);
                an[n] = fmaf(h, vn, an[n]);
            }
        }
#pragma unroll
        for (int off = 16; off > 0; off >>= 1) {
#pragma unroll
            for (int n = 0; n < 16; n++) {
                ar[n] += __shfl_xor_sync(0xffffffffu, ar[n], off);
                az[n] += __shfl_xor_sync(0xffffffffu, az[n], off);
                an[n] += __shfl_xor_sync(0xffffffffu, an[n], off);
            }
        }
        if (lane < 16) {
            int n = lane;
            const float* gir = gi + (size_t)(t * 16 + n) * 1536;
            float r  = 1.f / (1.f + expf(-(gir[j]        + ar[n] + bjr)));
            float z  = 1.f / (1.f + expf(-(gir[512 + j]  + az[n] + bjz)));
            float ng = tanhf(gir[1024 + j] + r * (an[n] + bjn));
            float hnew = (1.f - z) * ng + z * hs[n][j];
            __stcg(&hout[n * 512 + j], hnew);
            outs[(size_t)(t * 16 + n) * 512 + j] = hnew;
        }

        if (t < 31) {
            __syncthreads();
            __threadfence();
            if (tid == 0) {
                atomicAdd(&g_barrier_i, 1);
                int target = 128 * (t + 1);
                while (*((volatile int*)&g_barrier_i) < target) __nanosleep(32);
            }
            __syncthreads();
        }
    }
}

// ---------------------------------------------------------------------------
// Heads: per row, 6 logits + value, log_softmax, entropy, gathered logp.
// ---------------------------------------------------------------------------
__launch_bounds__(128)
__global__ void heads_kernel(const float* __restrict__ outs,
                             const float* __restrict__ aw, const float* __restrict__ ab,
                             const float* __restrict__ cw, const float* __restrict__ cb,
                             const int* __restrict__ action,
                             float* __restrict__ out)
{
    const int row = blockIdx.x;
    const float* x = outs + (size_t)row * 512;
    float acc[7];
#pragma unroll
    for (int g = 0; g < 7; g++) acc[g] = 0.f;
    for (int k = threadIdx.x; k < 512; k += 128) {
        float xv = x[k];
#pragma unroll
        for (int g = 0; g < 6; g++) acc[g] = fmaf(xv, aw[g * 512 + k], acc[g]);
        acc[6] = fmaf(xv, cw[k], acc[6]);
    }
#pragma unroll
    for (int off = 16; off > 0; off >>= 1)
#pragma unroll
        for (int g = 0; g < 7; g++) acc[g] += __shfl_xor_sync(0xffffffffu, acc[g], off);

    __shared__ float red[4][7];
    int warp = threadIdx.x >> 5, lane = threadIdx.x & 31;
    if (lane == 0)
        for (int g = 0; g < 7; g++) red[warp][g] = acc[g];
    __syncthreads();

    if (threadIdx.x == 0) {
        float l[6], v;
        for (int g = 0; g < 6; g++)
            l[g] = red[0][g] + red[1][g] + red[2][g] + red[3][g] + ab[g];
        v = red[0][6] + red[1][6] + red[2][6] + red[3][6] + cb[0];

        float mx = l[0];
        for (int g = 1; g < 6; g++) mx = fmaxf(mx, l[g]);
        float se = 0.f;
        for (int g = 0; g < 6; g++) se += expf(l[g] - mx);
        float lse = logf(se) + mx;
        float ent = 0.f;
        for (int g = 0; g < 6; g++) { float lp = l[g] - lse; ent -= expf(lp) * lp; }

        int a = action[row];
        if (a < 0) a = 0;
        if (a > 5) a = 5;
        out[row]        = v;
        out[512 + row]  = l[a] - lse;
        out[1024 + row] = ent;
    }
}

__global__ void copy_states_kernel(const float* __restrict__ h, float* __restrict__ out)
{
    int i = blockIdx.x * blockDim.x + threadIdx.x;
    if (i < 16 * 512) out[1536 + i] = h[i];
}

// ---------------------------------------------------------------------------
extern "C" void kernel_launch(void* const* d_in, const int* in_sizes, int n_in,
                              void* d_out, int out_size)
{
    (void)in_sizes; (void)n_in; (void)out_size;
    const float* inputs = (const float*)d_in[0];
    const float* states = (const float*)d_in[1];
    const float* masks  = (const float*)d_in[2];
    const int*   action = (const int*)d_in[3];
    const float* c1w = (const float*)d_in[4];
    const float* c1b = (const float*)d_in[5];
    const float* c2w = (const float*)d_in[6];
    const float* c2b = (const float*)d_in[7];
    const float* c3w = (const float*)d_in[8];
    const float* c3b = (const float*)d_in[9];
    const float* fcw = (const float*)d_in[10];
    const float* fcb = (const float*)d_in[11];
    const float* wih = (const float*)d_in[12];
    const float* whh = (const float*)d_in[13];
    const float* bih = (const float*)d_in[14];
    const float* bhh = (const float*)d_in[15];
    const float* aw  = (const float*)d_in[16];
    const float* ab  = (const float*)d_in[17];
    const float* cw  = (const float*)d_in[18];
    const float* cb  = (const float*)d_in[19];
    float* out = (float*)d_out;

    float *act1, *act2, *xfc, *part, *xb, *gi, *hbase, *outs;
    cudaGetSymbolAddress((void**)&act1,  g_act1);
    cudaGetSymbolAddress((void**)&act2,  g_act2);
    cudaGetSymbolAddress((void**)&xfc,   g_xfc);
    cudaGetSymbolAddress((void**)&part,  g_part);
    cudaGetSymbolAddress((void**)&xb,    g_x);
    cudaGetSymbolAddress((void**)&gi,    g_gi);
    cudaGetSymbolAddress((void**)&hbase, g_h);
    cudaGetSymbolAddress((void**)&outs,  g_outs);
    float* h0 = hbase;
    float* h1 = hbase + 16 * 512;

    // conv1: 4->32, 8x8 s4, NCHW [512][4][124][124] -> act1 [32][460800]
    conv_mma_kernel<4, 8, 124, 30, 4, 124 * 124, 4 * 124 * 124, 32, true, false>
        <<<1800, 256>>>(c1w, c1b, inputs, act1);

    // conv2: 32->64, 4x4 s2, act1 [c][img*900+s] -> act2 [64][100352]
    conv_mma_kernel<32, 4, 30, 14, 2, 512 * 900, 900, 64, false, false>
        <<<392, 256>>>(c2w, c2b, act1, act2);

    // conv3: 64->32, 3x3 s1, act2 [c][img*196+s] -> xfc [img][c*144+s] (direct)
    conv_mma_kernel<64, 3, 14, 12, 1, 512 * 196, 196, 32, false, true>
        <<<288, 256>>>(c3w, c3b, act2, xfc);

    // fc: [512,4608] x [512,4608]^T, split-K 8 (kps=576)
    gemm_nt_mma<64, 256><<<dim3(2, 8, 8), 256>>>(xfc, fcw, part, 512, 512, 4608, 576);
    finalize_kernel<<<1024, 256>>>(part, 8, fcb, xb, 512 * 512, 512, 1);

    // gi: [512,512] x [1536,512]^T, split-K 2 (kps=256)
    gemm_nt_mma<64, 256><<<dim3(6, 8, 2), 256>>>(xb, wih, part, 512, 1536, 512, 256);
    finalize_kernel<<<3072, 256>>>(part, 2, bih, gi, 512 * 1536, 1536, 0);

    // GRU recurrence: single persistent kernel with grid-wide step barrier
    zero_barrier_kernel<<<1, 1>>>();
    gru_persistent_kernel<<<128, 128>>>(gi, whh, bhh, masks, states, h0, h1, outs);

    // heads + outputs (final hidden state is in h1: t=31 writes buf[31&1])
    heads_kernel<<<512, 128>>>(outs, aw, ab, cw, cb, action, out);
    copy_states_kernel<<<32, 256>>>(h1, out);
}

// round 6
// speedup vs baseline: 1.2945x; 1.0004x over previous
#include <cuda_runtime.h>
#include <math.h>

// ---------------------------------------------------------------------------
// Problem constants
//   T=32, N=16, TN=512, C=4, HW=124, A=6, H=512
//   conv1: 4->32, 8x8 s4 : 124 -> 30   (K=256,  N=512*900 =460800)
//   conv2: 32->64, 4x4 s2: 30 -> 14    (K=512,  N=512*196 =100352)
//   conv3: 64->32, 3x3 s1: 14 -> 12    (K=576,  N=512*144 = 73728)
//   fc: 4608 -> 512 ; GRU H=512 ; heads A=6 + value
// Output (9728 f32): value[512] | alp[512] | entropy[512] | states_out[16*512]
// ---------------------------------------------------------------------------

__device__ float g_act1[32 * 512 * 900];    // conv1 out [oc][img*900+s]
__device__ float g_act2[64 * 512 * 196];    // conv2 out [oc][img*196+s]
__device__ float g_xfc[512 * 4608];         // conv3 out in fc layout [img][c*144+s]
__device__ float g_part[8 * 512 * 1536];    // split-K partials (fc / gi)
__device__ float g_x[512 * 512];            // fc output (relu)
__device__ float g_gi[512 * 1536];          // input gates [t*16+n][1536]
__device__ float g_h[2][16 * 512];          // GRU hidden ping-pong
__device__ float g_outs[512 * 512];         // GRU outputs [t*16+n][512]
__device__ int   g_barrier_i;

// ------------------------------ tf32 helpers -------------------------------
__device__ __forceinline__ unsigned f2tf32(float f) {
    unsigned u;
    asm("cvt.rna.tf32.f32 %0, %1;" : "=r"(u) : "f"(f));
    return u;
}

__device__ __forceinline__ void mma_tf32(float& c0, float& c1, float& c2, float& c3,
                                         unsigned a0, unsigned a1, unsigned a2, unsigned a3,
                                         unsigned b0, unsigned b1)
{
    asm volatile(
        "mma.sync.aligned.m16n8k8.row.col.f32.tf32.tf32.f32 "
        "{%0,%1,%2,%3},{%4,%5,%6,%7},{%8,%9},{%0,%1,%2,%3};"
        : "+f"(c0), "+f"(c1), "+f"(c2), "+f"(c3)
        : "r"(a0), "r"(a1), "r"(a2), "r"(a3), "r"(b0), "r"(b1));
}

// ---------------------------------------------------------------------------
// TF32 implicit-im2col conv GEMM.
//   out[m][n] = relu(sum_k W[m][k]*col[k][n] + b[m]),  m = OC row, n = (img, oy, ox)
//   BM == OC, BN = 256, BK = 32. 256 threads, 8 warps, warp tile 32 x WN.
//   Fragment layouts: mma.m16n8k8 tf32 (Ampere-standard).
// ---------------------------------------------------------------------------
template<int C, int KK, int IW, int OW, int STRIDE,
         int CH_STRIDE, int IMG_STRIDE,
         int BM, bool SCALE, bool XFC_OUT>
__launch_bounds__(256)
__global__ void conv_mma_kernel(const float* __restrict__ W,
                                const float* __restrict__ bias,
                                const float* __restrict__ in,
                                float* __restrict__ out)
{
    constexpr int K     = C * KK * KK;
    constexpr int SPER  = OW * OW;
    constexpr int NTOT  = 512 * SPER;
    constexpr int BN    = 256;
    constexpr int BK    = 32;
    constexpr int WARPS_M = BM / 32;
    constexpr int WARPS_N = 8 / WARPS_M;
    constexpr int WN      = BN / WARPS_N;
    constexpr int NFRAG   = WN / 8;

    __shared__ unsigned As[BM][36];   // [m][k] tf32 bits
    __shared__ unsigned Bs[BN][36];   // [n][k] tf32 bits
    __shared__ int nb[BN];

    const int tid  = threadIdx.x;
    const int bn0  = blockIdx.x * BN;
    const int warp = tid >> 5, lane = tid & 31;
    const int g = lane >> 2, t4 = lane & 3;
    const int warp_m = warp / WARPS_N, warp_n = warp % WARPS_N;
    const int m_base = warp_m * 32, n_base = warp_n * WN;

    for (int i = tid; i < BN; i += 256) {
        int ng  = bn0 + i;
        int img = ng / SPER;
        int r   = ng - img * SPER;
        int oy  = r / OW;
        int ox  = r - oy * OW;
        nb[i] = img * IMG_STRIDE + oy * STRIDE * IW + ox * STRIDE;
    }
    __syncthreads();

    float acc[2][NFRAG][4];
#pragma unroll
    for (int mt = 0; mt < 2; mt++)
#pragma unroll
        for (int nf = 0; nf < NFRAG; nf++)
#pragma unroll
            for (int q = 0; q < 4; q++) acc[mt][nf][q] = 0.f;

    for (int k0 = 0; k0 < K; k0 += BK) {
        // A tile (weights), coalesced per m-row
        for (int idx = tid; idx < BM * BK; idx += 256) {
            int m = idx >> 5, kk = idx & 31;
            As[m][kk] = f2tf32(W[m * K + k0 + kk]);
        }
        // B tile: implicit im2col gather (n fastest -> coalesced gmem)
        for (int idx = tid; idx < BK * BN; idx += 256) {
            int kk = idx >> 8, nn = idx & (BN - 1);
            int kg = k0 + kk;
            int c  = kg / (KK * KK);
            int r  = kg - c * (KK * KK);
            int ky = r / KK, kx = r - ky * KK;
            float v = __ldg(&in[nb[nn] + c * CH_STRIDE + ky * IW + kx]);
            Bs[nn][kk] = f2tf32(SCALE ? v * (1.0f / 255.0f) : v);
        }
        __syncthreads();

#pragma unroll
        for (int ks = 0; ks < 4; ks++) {
            const int kl = ks * 8;
            unsigned a[2][4];
#pragma unroll
            for (int mt = 0; mt < 2; mt++) {
                int mr = m_base + mt * 16 + g;
                a[mt][0] = As[mr][kl + t4];
                a[mt][1] = As[mr + 8][kl + t4];
                a[mt][2] = As[mr][kl + t4 + 4];
                a[mt][3] = As[mr + 8][kl + t4 + 4];
            }
#pragma unroll
            for (int nf = 0; nf < NFRAG; nf++) {
                int nr = n_base + nf * 8 + g;
                unsigned b0 = Bs[nr][kl + t4];
                unsigned b1 = Bs[nr][kl + t4 + 4];
#pragma unroll
                for (int mt = 0; mt < 2; mt++)
                    mma_tf32(acc[mt][nf][0], acc[mt][nf][1], acc[mt][nf][2], acc[mt][nf][3],
                             a[mt][0], a[mt][1], a[mt][2], a[mt][3], b0, b1);
            }
        }
        __syncthreads();
    }

    // epilogue
#pragma unroll
    for (int mt = 0; mt < 2; mt++) {
        int m0g = m_base + mt * 16 + g;
        float b0 = bias[m0g];
        float b1 = bias[m0g + 8];
#pragma unroll
        for (int nf = 0; nf < NFRAG; nf++) {
            int n = bn0 + n_base + nf * 8 + t4 * 2;
            float v00 = fmaxf(acc[mt][nf][0] + b0, 0.f);
            float v01 = fmaxf(acc[mt][nf][1] + b0, 0.f);
            float v10 = fmaxf(acc[mt][nf][2] + b1, 0.f);
            float v11 = fmaxf(acc[mt][nf][3] + b1, 0.f);
            if (XFC_OUT) {
                int img = n / SPER, s = n - img * SPER;
                out[img * (32 * SPER) + m0g * SPER + s]           = v00;
                out[img * (32 * SPER) + m0g * SPER + s + 1]       = v01;
                out[img * (32 * SPER) + (m0g + 8) * SPER + s]     = v10;
                out[img * (32 * SPER) + (m0g + 8) * SPER + s + 1] = v11;
            } else {
                out[(size_t)m0g * NTOT + n]           = v00;
                out[(size_t)m0g * NTOT + n + 1]       = v01;
                out[(size_t)(m0g + 8) * NTOT + n]     = v10;
                out[(size_t)(m0g + 8) * NTOT + n + 1] = v11;
            }
        }
    }
}

// ---------------------------------------------------------------------------
// TF32 NT GEMM with split-K: partial[z] = A[M][K] * B[N][K]^T over k slice.
// ---------------------------------------------------------------------------
template<int BM, int BN>
__launch_bounds__(256)
__global__ void gemm_nt_mma(const float* __restrict__ A, const float* __restrict__ B,
                            float* __restrict__ partial, int M, int N, int K, int kps)
{
    constexpr int BK = 32;
    constexpr int WARPS_M = BM / 32;
    constexpr int WARPS_N = 8 / WARPS_M;
    constexpr int WN      = BN / WARPS_N;
    constexpr int NFRAG   = WN / 8;

    __shared__ unsigned As[BM][36];
    __shared__ unsigned Bs[BN][36];

    const int tid  = threadIdx.x;
    const int m0   = blockIdx.y * BM, n0 = blockIdx.x * BN;
    const int kbeg = blockIdx.z * kps;
    const int warp = tid >> 5, lane = tid & 31;
    const int g = lane >> 2, t4 = lane & 3;
    const int warp_m = warp / WARPS_N, warp_n = warp % WARPS_N;
    const int m_base = warp_m * 32, n_base = warp_n * WN;

    float acc[2][NFRAG][4];
#pragma unroll
    for (int mt = 0; mt < 2; mt++)
#pragma unroll
        for (int nf = 0; nf < NFRAG; nf++)
#pragma unroll
            for (int q = 0; q < 4; q++) acc[mt][nf][q] = 0.f;

    for (int k0 = kbeg; k0 < kbeg + kps; k0 += BK) {
        for (int idx = tid; idx < BM * BK; idx += 256) {
            int m = idx >> 5, kk = idx & 31;
            As[m][kk] = f2tf32(A[(size_t)(m0 + m) * K + k0 + kk]);
        }
        for (int idx = tid; idx < BN * BK; idx += 256) {
            int n = idx >> 5, kk = idx & 31;
            Bs[n][kk] = f2tf32(B[(size_t)(n0 + n) * K + k0 + kk]);
        }
        __syncthreads();

#pragma unroll
        for (int ks = 0; ks < 4; ks++) {
            const int kl = ks * 8;
            unsigned a[2][4];
#pragma unroll
            for (int mt = 0; mt < 2; mt++) {
                int mr = m_base + mt * 16 + g;
                a[mt][0] = As[mr][kl + t4];
                a[mt][1] = As[mr + 8][kl + t4];
                a[mt][2] = As[mr][kl + t4 + 4];
                a[mt][3] = As[mr + 8][kl + t4 + 4];
            }
#pragma unroll
            for (int nf = 0; nf < NFRAG; nf++) {
                int nr = n_base + nf * 8 + g;
                unsigned b0 = Bs[nr][kl + t4];
                unsigned b1 = Bs[nr][kl + t4 + 4];
#pragma unroll
                for (int mt = 0; mt < 2; mt++)
                    mma_tf32(acc[mt][nf][0], acc[mt][nf][1], acc[mt][nf][2], acc[mt][nf][3],
                             a[mt][0], a[mt][1], a[mt][2], a[mt][3], b0, b1);
            }
        }
        __syncthreads();
    }

    float* p = partial + (size_t)blockIdx.z * M * N;
#pragma unroll
    for (int mt = 0; mt < 2; mt++) {
        int m = m0 + m_base + mt * 16 + g;
#pragma unroll
        for (int nf = 0; nf < NFRAG; nf++) {
            int n = n0 + n_base + nf * 8 + t4 * 2;
            p[(size_t)m * N + n]           = acc[mt][nf][0];
            p[(size_t)m * N + n + 1]       = acc[mt][nf][1];
            p[(size_t)(m + 8) * N + n]     = acc[mt][nf][2];
            p[(size_t)(m + 8) * N + n + 1] = acc[mt][nf][3];
        }
    }
}

__global__ void finalize_kernel(const float* __restrict__ partial, int S,
                                const float* __restrict__ bias,
                                float* __restrict__ out, int MN, int N, int relu)
{
    for (int i = blockIdx.x * blockDim.x + threadIdx.x; i < MN;
         i += gridDim.x * blockDim.x) {
        float v = 0.f;
        for (int s = 0; s < S; s++) v += partial[(size_t)s * MN + i];
        v += bias[i % N];
        out[i] = relu ? fmaxf(v, 0.f) : v;
    }
}

__global__ void zero_barrier_kernel() { g_barrier_i = 0; }

// ---------------------------------------------------------------------------
// Persistent GRU: 128 blocks x 128 threads. warp -> hidden column j.
// w_hh rows held in registers; per-step grid barrier via atomic counter.
// h ping-pong through L2 (__ldcg/__stcg) since L1 is not coherent.
// ---------------------------------------------------------------------------
__launch_bounds__(128)
__global__ void gru_persistent_kernel(const float* __restrict__ gi,
                                      const float* __restrict__ w_hh,
                                      const float* __restrict__ b_hh,
                                      const float* __restrict__ masks,
                                      const float* __restrict__ states,
                                      float* __restrict__ h0,
                                      float* __restrict__ h1,
                                      float* __restrict__ outs)
{
    __shared__ float hs[16][512];
    const int tid = threadIdx.x;
    const int warp = tid >> 5, lane = tid & 31;
    const int j = blockIdx.x * 4 + warp;    // 0..511

    float wr[16], wz[16], wn[16];
    const float* wrp = w_hh + (size_t)j * 512;
    const float* wzp = w_hh + (size_t)(512 + j) * 512;
    const float* wnp = w_hh + (size_t)(1024 + j) * 512;
#pragma unroll
    for (int i = 0; i < 16; i++) {
        int k = i * 32 + lane;
        wr[i] = __ldg(&wrp[k]);
        wz[i] = __ldg(&wzp[k]);
        wn[i] = __ldg(&wnp[k]);
    }
    const float bjr = b_hh[j], bjz = b_hh[512 + j], bjn = b_hh[1024 + j];

    for (int t = 0; t < 32; t++) {
        const float* hin = (t == 0) ? states : (((t & 1) == 1) ? h0 : h1);
        float* hout = (t & 1) ? h1 : h0;

        for (int i = tid; i < 16 * 512; i += 128) {
            int n = i >> 9;
            hs[n][i & 511] = __ldcg(&hin[i]) * masks[t * 16 + n];
        }
        __syncthreads();

        float ar[16], az[16], an[16];
#pragma unroll
        for (int n = 0; n < 16; n++) { ar[n] = 0.f; az[n] = 0.f; an[n] = 0.f; }

#pragma unroll
        for (int i = 0; i < 16; i++) {
            int k = i * 32 + lane;
            float vr = wr[i], vz = wz[i], vn = wn[i];
#pragma unroll
            for (int n = 0; n < 16; n++) {
                float h = hs[n][k];
                ar[n] = fmaf(h, vr, ar[n]);
                az[n] = fmaf(h, vz, az[n]);
                an[n] = fmaf(h, vn, an[n]);
            }
        }
#pragma unroll
        for (int off = 16; off > 0; off >>= 1) {
#pragma unroll
            for (int n = 0; n < 16; n++) {
                ar[n] += __shfl_xor_sync(0xffffffffu, ar[n], off);
                az[n] += __shfl_xor_sync(0xffffffffu, az[n], off);
                an[n] += __shfl_xor_sync(0xffffffffu, an[n], off);
            }
        }
        if (lane < 16) {
            int n = lane;
            const float* gir = gi + (size_t)(t * 16 + n) * 1536;
            float r  = 1.f / (1.f + expf(-(gir[j]        + ar[n] + bjr)));
            float z  = 1.f / (1.f + expf(-(gir[512 + j]  + az[n] + bjz)));
            float ng = tanhf(gir[1024 + j] + r * (an[n] + bjn));
            float hnew = (1.f - z) * ng + z * hs[n][j];
            __stcg(&hout[n * 512 + j], hnew);
            outs[(size_t)(t * 16 + n) * 512 + j] = hnew;
        }

        if (t < 31) {
            __syncthreads();
            __threadfence();
            if (tid == 0) {
                atomicAdd(&g_barrier_i, 1);
                int target = 128 * (t + 1);
                while (*((volatile int*)&g_barrier_i) < target) __nanosleep(32);
            }
            __syncthreads();
        }
    }
}

// ---------------------------------------------------------------------------
// Heads: per row, 6 logits + value, log_softmax, entropy, gathered logp.
// ---------------------------------------------------------------------------
__launch_bounds__(128)
__global__ void heads_kernel(const float* __restrict__ outs,
                             const float* __restrict__ aw, const float* __restrict__ ab,
                             const float* __restrict__ cw, const float* __restrict__ cb,
                             const int* __restrict__ action,
                             float* __restrict__ out)
{
    const int row = blockIdx.x;
    const float* x = outs + (size_t)row * 512;
    float acc[7];
#pragma unroll
    for (int g = 0; g < 7; g++) acc[g] = 0.f;
    for (int k = threadIdx.x; k < 512; k += 128) {
        float xv = x[k];
#pragma unroll
        for (int g = 0; g < 6; g++) acc[g] = fmaf(xv, aw[g * 512 + k], acc[g]);
        acc[6] = fmaf(xv, cw[k], acc[6]);
    }
#pragma unroll
    for (int off = 16; off > 0; off >>= 1)
#pragma unroll
        for (int g = 0; g < 7; g++) acc[g] += __shfl_xor_sync(0xffffffffu, acc[g], off);

    __shared__ float red[4][7];
    int warp = threadIdx.x >> 5, lane = threadIdx.x & 31;
    if (lane == 0)
        for (int g = 0; g < 7; g++) red[warp][g] = acc[g];
    __syncthreads();

    if (threadIdx.x == 0) {
        float l[6], v;
        for (int g = 0; g < 6; g++)
            l[g] = red[0][g] + red[1][g] + red[2][g] + red[3][g] + ab[g];
        v = red[0][6] + red[1][6] + red[2][6] + red[3][6] + cb[0];

        float mx = l[0];
        for (int g = 1; g < 6; g++) mx = fmaxf(mx, l[g]);
        float se = 0.f;
        for (int g = 0; g < 6; g++) se += expf(l[g] - mx);
        float lse = logf(se) + mx;
        float ent = 0.f;
        for (int g = 0; g < 6; g++) { float lp = l[g] - lse; ent -= expf(lp) * lp; }

        int a = action[row];
        if (a < 0) a = 0;
        if (a > 5) a = 5;
        out[row]        = v;
        out[512 + row]  = l[a] - lse;
        out[1024 + row] = ent;
    }
}

__global__ void copy_states_kernel(const float* __restrict__ h, float* __restrict__ out)
{
    int i = blockIdx.x * blockDim.x + threadIdx.x;
    if (i < 16 * 512) out[1536 + i] = h[i];
}

// ---------------------------------------------------------------------------
extern "C" void kernel_launch(void* const* d_in, const int* in_sizes, int n_in,
                              void* d_out, int out_size)
{
    (void)in_sizes; (void)n_in; (void)out_size;
    const float* inputs = (const float*)d_in[0];
    const float* states = (const float*)d_in[1];
    const float* masks  = (const float*)d_in[2];
    const int*   action = (const int*)d_in[3];
    const float* c1w = (const float*)d_in[4];
    const float* c1b = (const float*)d_in[5];
    const float* c2w = (const float*)d_in[6];
    const float* c2b = (const float*)d_in[7];
    const float* c3w = (const float*)d_in[8];
    const float* c3b = (const float*)d_in[9];
    const float* fcw = (const float*)d_in[10];
    const float* fcb = (const float*)d_in[11];
    const float* wih = (const float*)d_in[12];
    const float* whh = (const float*)d_in[13];
    const float* bih = (const float*)d_in[14];
    const float* bhh = (const float*)d_in[15];
    const float* aw  = (const float*)d_in[16];
    const float* ab  = (const float*)d_in[17];
    const float* cw  = (const float*)d_in[18];
    const float* cb  = (const float*)d_in[19];
    float* out = (float*)d_out;

    float *act1, *act2, *xfc, *part, *xb, *gi, *hbase, *outs;
    cudaGetSymbolAddress((void**)&act1,  g_act1);
    cudaGetSymbolAddress((void**)&act2,  g_act2);
    cudaGetSymbolAddress((void**)&xfc,   g_xfc);
    cudaGetSymbolAddress((void**)&part,  g_part);
    cudaGetSymbolAddress((void**)&xb,    g_x);
    cudaGetSymbolAddress((void**)&gi,    g_gi);
    cudaGetSymbolAddress((void**)&hbase, g_h);
    cudaGetSymbolAddress((void**)&outs,  g_outs);
    float* h0 = hbase;
    float* h1 = hbase + 16 * 512;

    // conv1: 4->32, 8x8 s4, NCHW [512][4][124][124] -> act1 [32][460800]
    conv_mma_kernel<4, 8, 124, 30, 4, 124 * 124, 4 * 124 * 124, 32, true, false>
        <<<1800, 256>>>(c1w, c1b, inputs, act1);

    // conv2: 32->64, 4x4 s2, act1 [c][img*900+s] -> act2 [64][100352]
    conv_mma_kernel<32, 4, 30, 14, 2, 512 * 900, 900, 64, false, false>
        <<<392, 256>>>(c2w, c2b, act1, act2);

    // conv3: 64->32, 3x3 s1, act2 [c][img*196+s] -> xfc [img][c*144+s] (direct)
    conv_mma_kernel<64, 3, 14, 12, 1, 512 * 196, 196, 32, false, true>
        <<<288, 256>>>(c3w, c3b, act2, xfc);

    // fc: [512,4608] x [512,4608]^T, split-K 8 (kps=576)
    gemm_nt_mma<64, 256><<<dim3(2, 8, 8), 256>>>(xfc, fcw, part, 512, 512, 4608, 576);
    finalize_kernel<<<1024, 256>>>(part, 8, fcb, xb, 512 * 512, 512, 1);

    // gi: [512,512] x [1536,512]^T, split-K 2 (kps=256)
    gemm_nt_mma<64, 256><<<dim3(6, 8, 2), 256>>>(xb, wih, part, 512, 1536, 512, 256);
    finalize_kernel<<<3072, 256>>>(part, 2, bih, gi, 512 * 1536, 1536, 0);

    // GRU recurrence: single persistent kernel with grid-wide step barrier
    zero_barrier_kernel<<<1, 1>>>();
    gru_persistent_kernel<<<128, 128>>>(gi, whh, bhh, masks, states, h0, h1, outs);

    // heads + outputs (final hidden state is in h1: t=31 writes buf[31&1])
    heads_kernel<<<512, 128>>>(outs, aw, ab, cw, cb, action, out);
    copy_states_kernel<<<32, 256>>>(h1, out);
}